// round 4
// baseline (speedup 1.0000x reference)
#include <cuda_runtime.h>
#include <cuda_bf16.h>
#include <cstdint>
#include <math.h>

// POLY2: out[b] = sigmoid(w0 + x[b,:]@w1 + x[b,:]^T @ W2 @ x[b,:])
// B=16384, N=2048.
//
// R3 finding: harness toolchain targets BASE sm_100 (PTX compute_100) — all
// tcgen05/TMEM features rejected by ptxas. Portable tensor-core path instead:
// mma.sync.m16n8k16 bf16 with a 3-term error split
//   z  ~=  Xhi*Whi + Xhi*Wlo + Xlo*Whi     (fp32 accumulate, lo*lo dropped)
// which keeps |dz| ~ 1e-4 (vs sigma(z) ~ 45).
//
// Structure: prepass converts W2 -> bf16 hi/lo. Main kernel: CTA = 128 rows,
// 16 j-passes of 128 cols; k-chunks of 32 with 2-stage smem double buffer.
// B via cp.async (row-major [k][n], 272B padded rows, ldmatrix.x4.trans);
// A split from fp32 x in registers -> STS (80B padded rows, ldmatrix.x4).
// 8 warps (4m x 2n), warp tile 32x64. Epilogue: acc += (C + w1[n]) * x[m,n]
// folded from register fragments (linear term rides along); sigmoid at end.

static constexpr int Bsz = 16384;
static constexpr int Nsz = 2048;
static constexpr int BM  = 128;
static constexpr int BN  = 128;
static constexpr int BK  = 32;
static constexpr int NJP = Nsz / BN;   // 16 j-passes
static constexpr int NC  = Nsz / BK;   // 64 k-chunks
static constexpr int NT  = 256;        // 8 warps

// ---------------- device scratch: bf16 splits of W2 (16 MB) ----------------
__device__ __align__(16) __nv_bfloat16 g_whi[Nsz * Nsz];
__device__ __align__(16) __nv_bfloat16 g_wlo[Nsz * Nsz];

// ---------------- smem layout ----------------
static constexpr int A_STRIDE = 80;            // bytes/row: 32 bf16 = 64B + pad
static constexpr int A_SPLIT  = BM * A_STRIDE; // 10240
static constexpr int A_STAGE  = 2 * A_SPLIT;   // hi+lo, 20480
static constexpr int B_STRIDE = 272;           // bytes/k-row: 128 bf16 = 256B + pad
static constexpr int B_SPLIT  = BK * B_STRIDE; // 8704
static constexpr int B_STAGE  = 2 * B_SPLIT;   // 17408
static constexpr int SM_A     = 1024;          // [0,512) = acc_row
static constexpr int SM_B     = SM_A + 2 * A_STAGE;    // 41984
static constexpr int SM_TOTAL = SM_B + 2 * B_STAGE;    // 76800

// ---------------- helpers ----------------
__device__ __forceinline__ uint32_t smem_u32(const void* p) {
    uint32_t a;
    asm("{ .reg .u64 t; cvta.to.shared.u64 t, %1; cvt.u32.u64 %0, t; }" : "=r"(a) : "l"(p));
    return a;
}
#define CP_ASYNC16(dst, src) asm volatile("cp.async.cg.shared.global [%0], [%1], 16;" :: "r"(dst), "l"(src) : "memory")
#define CP_COMMIT()          asm volatile("cp.async.commit_group;" ::: "memory")
#define CP_WAIT0()           asm volatile("cp.async.wait_group 0;" ::: "memory")

__device__ __forceinline__ void ldmx4(uint32_t r[4], uint32_t addr) {
    asm volatile("ldmatrix.sync.aligned.m8n8.x4.shared.b16 {%0,%1,%2,%3}, [%4];"
                 : "=r"(r[0]), "=r"(r[1]), "=r"(r[2]), "=r"(r[3]) : "r"(addr));
}
__device__ __forceinline__ void ldmx4t(uint32_t r[4], uint32_t addr) {
    asm volatile("ldmatrix.sync.aligned.m8n8.x4.trans.shared.b16 {%0,%1,%2,%3}, [%4];"
                 : "=r"(r[0]), "=r"(r[1]), "=r"(r[2]), "=r"(r[3]) : "r"(addr));
}
__device__ __forceinline__ void mma_bf16(float c[4], const uint32_t a[4],
                                         uint32_t b0, uint32_t b1) {
    asm volatile("mma.sync.aligned.m16n8k16.row.col.f32.bf16.bf16.f32 "
                 "{%0,%1,%2,%3}, {%4,%5,%6,%7}, {%8,%9}, {%0,%1,%2,%3};"
                 : "+f"(c[0]), "+f"(c[1]), "+f"(c[2]), "+f"(c[3])
                 : "r"(a[0]), "r"(a[1]), "r"(a[2]), "r"(a[3]), "r"(b0), "r"(b1));
}
__device__ __forceinline__ uint32_t pack_bf2(__nv_bfloat16 a, __nv_bfloat16 b) {
    __nv_bfloat162 v(a, b);
    return *reinterpret_cast<uint32_t*>(&v);
}

// =======================================================================
__global__ void convert_w_kernel(const float* __restrict__ w2) {
    int i = blockIdx.x * blockDim.x + threadIdx.x;   // float4 index
    const float4 v = reinterpret_cast<const float4*>(w2)[i];
    float f[4] = {v.x, v.y, v.z, v.w};
    __nv_bfloat16 hi[4], lo[4];
#pragma unroll
    for (int k = 0; k < 4; k++) {
        hi[k] = __float2bfloat16(f[k]);
        lo[k] = __float2bfloat16(f[k] - __bfloat162float(hi[k]));
    }
    uint2 ph, pl;
    ph.x = pack_bf2(hi[0], hi[1]); ph.y = pack_bf2(hi[2], hi[3]);
    pl.x = pack_bf2(lo[0], lo[1]); pl.y = pack_bf2(lo[2], lo[3]);
    reinterpret_cast<uint2*>(g_whi)[i] = ph;
    reinterpret_cast<uint2*>(g_wlo)[i] = pl;
}

// =======================================================================
__global__ void __launch_bounds__(NT)
poly2_mma_kernel(const float* __restrict__ x,
                 const float* __restrict__ w0,
                 const float* __restrict__ w1,
                 float* __restrict__ out)
{
    extern __shared__ char smem[];
    const uint32_t sb = smem_u32(smem);
    float* acc_row = reinterpret_cast<float*>(smem);

    const int tid  = threadIdx.x;
    const int lane = tid & 31, wid = tid >> 5;
    const int gid  = lane >> 2, tig = lane & 3;
    const int warp_m = wid & 3;       // 0..3 -> m offset *32
    const int warp_n = wid >> 2;      // 0..1 -> n offset *64
    const int row0 = blockIdx.x * BM;

    if (tid < BM) acc_row[tid] = 0.0f;
    __syncthreads();

    // ldmatrix per-lane address components (constant across chunks)
    const int blk = lane >> 3, rr = lane & 7;
    const int a_mrow0 = warp_m * 32 + (blk & 1) * 8 + rr;   // + mi*16
    const int a_kcol0 = (blk >> 1) * 8;                     // + h*16
    const int b_krow0 = (blk & 1) * 8 + rr;                 // + h*16
    const int b_ncol0 = warp_n * 64 + (blk >> 1) * 8;       // + nb2*16

    float accp[4] = {0.f, 0.f, 0.f, 0.f};   // row-slots: warp_m*32+mi*16+rh*8+gid

    for (int jp = 0; jp < NJP; jp++) {
        const int jt = jp * BN;
        float C[2][8][4];
#pragma unroll
        for (int a = 0; a < 2; a++)
#pragma unroll
            for (int b = 0; b < 8; b++)
#pragma unroll
                for (int q = 0; q < 4; q++) C[a][b][q] = 0.f;

        // ---- loaders (lambdas) ----
        auto loadB = [&](int c, int buf) {
            const uint32_t bb = sb + SM_B + buf * B_STAGE;
            const int kc = c * BK;
#pragma unroll
            for (int i = 0; i < 4; i++) {
                const int q   = tid + i * NT;        // 0..1023
                const int sp  = q >> 9;
                const int rem = q & 511;
                const int k   = rem >> 4;            // 0..31
                const int ch  = rem & 15;            // 16B chunk -> 8 n
                const __nv_bfloat16* src =
                    (sp ? g_wlo : g_whi) + (size_t)(kc + k) * Nsz + jt + ch * 8;
                CP_ASYNC16(bb + sp * B_SPLIT + k * B_STRIDE + ch * 16, src);
            }
            CP_COMMIT();
        };
        auto loadA_regs = [&](int c, float4* ar) {
            const int kc = c * BK;
#pragma unroll
            for (int i = 0; i < 2; i++) {
                const int p  = tid + i * NT;         // 0..511
                const int m  = p >> 2;
                const int kq = (p & 3) * 8;
                const float* xr = x + (size_t)(row0 + m) * Nsz + kc + kq;
                ar[i * 2 + 0] = *reinterpret_cast<const float4*>(xr);
                ar[i * 2 + 1] = *reinterpret_cast<const float4*>(xr + 4);
            }
        };
        auto stsA = [&](const float4* ar, int buf) {
            const uint32_t aHi = sb + SM_A + buf * A_STAGE;
            const uint32_t aLo = aHi + A_SPLIT;
#pragma unroll
            for (int i = 0; i < 2; i++) {
                const int p  = tid + i * NT;
                const int m  = p >> 2;
                const int kq = (p & 3) * 8;
                float f[8] = {ar[i*2].x, ar[i*2].y, ar[i*2].z, ar[i*2].w,
                              ar[i*2+1].x, ar[i*2+1].y, ar[i*2+1].z, ar[i*2+1].w};
                __nv_bfloat16 h[8], l[8];
#pragma unroll
                for (int k = 0; k < 8; k++) {
                    h[k] = __float2bfloat16(f[k]);
                    l[k] = __float2bfloat16(f[k] - __bfloat162float(h[k]));
                }
                const uint32_t off = m * A_STRIDE + kq * 2;
                asm volatile("st.shared.v4.b32 [%0], {%1,%2,%3,%4};"
                    :: "r"(aHi + off), "r"(pack_bf2(h[0],h[1])), "r"(pack_bf2(h[2],h[3])),
                       "r"(pack_bf2(h[4],h[5])), "r"(pack_bf2(h[6],h[7])) : "memory");
                asm volatile("st.shared.v4.b32 [%0], {%1,%2,%3,%4};"
                    :: "r"(aLo + off), "r"(pack_bf2(l[0],l[1])), "r"(pack_bf2(l[2],l[3])),
                       "r"(pack_bf2(l[4],l[5])), "r"(pack_bf2(l[6],l[7])) : "memory");
            }
        };

        // ---- prologue: fill stage 0 ----
        {
            float4 ar[4];
            loadB(0, 0);
            loadA_regs(0, ar);
            CP_WAIT0();
            stsA(ar, 0);
            __syncthreads();
        }

        // ---- mainloop ----
        for (int c = 0; c < NC; c++) {
            const int buf = c & 1;
            float4 arn[4];
            if (c + 1 < NC) { loadB(c + 1, buf ^ 1); loadA_regs(c + 1, arn); }

            const uint32_t aHi = sb + SM_A + buf * A_STAGE;
            const uint32_t aLo = aHi + A_SPLIT;
            const uint32_t bHi = sb + SM_B + buf * B_STAGE;
            const uint32_t bLo = bHi + B_SPLIT;
#pragma unroll
            for (int h = 0; h < 2; h++) {
                uint32_t Ah[2][4], Al[2][4];
#pragma unroll
                for (int mi = 0; mi < 2; mi++) {
                    const uint32_t aoff = (a_mrow0 + mi * 16) * A_STRIDE + (a_kcol0 + h * 16) * 2;
                    ldmx4(Ah[mi], aHi + aoff);
                    ldmx4(Al[mi], aLo + aoff);
                }
#pragma unroll
                for (int nb2 = 0; nb2 < 4; nb2++) {
                    const uint32_t boff = (b_krow0 + h * 16) * B_STRIDE + (b_ncol0 + nb2 * 16) * 2;
                    uint32_t Bh[4], Bl[4];
                    ldmx4t(Bh, bHi + boff);
                    ldmx4t(Bl, bLo + boff);
#pragma unroll
                    for (int mi = 0; mi < 2; mi++) {
#pragma unroll
                        for (int j = 0; j < 2; j++) {
                            float* cc = C[mi][nb2 * 2 + j];
                            mma_bf16(cc, Ah[mi], Bh[2*j], Bh[2*j+1]);
                            mma_bf16(cc, Ah[mi], Bl[2*j], Bl[2*j+1]);
                            mma_bf16(cc, Al[mi], Bh[2*j], Bh[2*j+1]);
                        }
                    }
                }
            }

            if (c + 1 < NC) { CP_WAIT0(); stsA(arn, buf ^ 1); }
            __syncthreads();
        }

        // ---- epilogue: fold (C + w1) * x into per-thread row partials ----
#pragma unroll
        for (int mi = 0; mi < 2; mi++) {
#pragma unroll
            for (int nb = 0; nb < 8; nb++) {
                const int ncol = jt + warp_n * 64 + nb * 8 + tig * 2;
                const float2 wv = *reinterpret_cast<const float2*>(w1 + ncol);
#pragma unroll
                for (int rh = 0; rh < 2; rh++) {
                    const int mrow = row0 + warp_m * 32 + mi * 16 + rh * 8 + gid;
                    const float2 xv = *reinterpret_cast<const float2*>(
                        x + (size_t)mrow * Nsz + ncol);
                    const float c0 = C[mi][nb][rh * 2 + 0];
                    const float c1 = C[mi][nb][rh * 2 + 1];
                    accp[mi * 2 + rh] = fmaf(c0 + wv.x, xv.x,
                                        fmaf(c1 + wv.y, xv.y, accp[mi * 2 + rh]));
                }
            }
        }
    }

    // ---- final per-row reduction + sigmoid ----
#pragma unroll
    for (int s = 0; s < 4; s++) {
        const int r = warp_m * 32 + (s >> 1) * 16 + (s & 1) * 8 + gid;
        atomicAdd(&acc_row[r], accp[s]);
    }
    __syncthreads();
    if (tid < BM) {
        const float z = w0[0] + acc_row[tid];
        out[row0 + tid] = 1.0f / (1.0f + __expf(-z));
    }
}

// =======================================================================
extern "C" void kernel_launch(void* const* d_in, const int* in_sizes, int n_in,
                              void* d_out, int out_size)
{
    const float* x  = (const float*)d_in[0];   // [16384, 2048]
    const float* w0 = (const float*)d_in[1];   // [1, 1]
    const float* w1 = (const float*)d_in[2];   // [2048, 1]
    const float* w2 = (const float*)d_in[3];   // [2048, 2048]
    float* out = (float*)d_out;                // [16384]

    cudaFuncSetAttribute(poly2_mma_kernel,
                         cudaFuncAttributeMaxDynamicSharedMemorySize, SM_TOTAL);

    convert_w_kernel<<<(Nsz * Nsz / 4) / 256, 256>>>(w2);
    poly2_mma_kernel<<<Bsz / BM, NT, SM_TOTAL>>>(x, w0, w1, out);
}